// round 2
// baseline (speedup 1.0000x reference)
#include <cuda_runtime.h>
#include <math.h>

// Problem constants (fixed by the reference)
#define DIM    2048     // D
#define NE     128      // experts
#define KSEL   4        // top-k
#define BM     64       // tokens per CTA
#define KC     32       // K chunk (fp32 elems)
#define AS     36       // smem row stride (floats), bank-conflict-free fragments
#define LST    129      // logits smem stride

// Split fp32 into tf32 hi + tf32 lo (x = hi + lo + O(2^-33 x))
__device__ __forceinline__ void split_tf32(float v, float& hi, float& lo) {
    unsigned h, l;
    asm("cvt.rna.tf32.f32 %0, %1;" : "=r"(h) : "f"(v));
    hi = __uint_as_float(h);
    float r = v - hi;  // exact (Sterbenz-style: fits in fp32)
    asm("cvt.rna.tf32.f32 %0, %1;" : "=r"(l) : "f"(r));
    lo = __uint_as_float(l);
}

__device__ __forceinline__ void mma_tf32(float c[4],
                                         unsigned a0, unsigned a1, unsigned a2, unsigned a3,
                                         unsigned b0, unsigned b1) {
    asm volatile(
        "mma.sync.aligned.m16n8k8.row.col.f32.tf32.tf32.f32 "
        "{%0,%1,%2,%3}, {%4,%5,%6,%7}, {%8,%9}, {%0,%1,%2,%3};\n"
        : "+f"(c[0]), "+f"(c[1]), "+f"(c[2]), "+f"(c[3])
        : "r"(a0), "r"(a1), "r"(a2), "r"(a3), "r"(b0), "r"(b1));
}

// One mma pass over a KC chunk into accumulator set `dst` (2 M-tiles x 4 N-tiles)
__device__ __forceinline__ void pass_chunk(float dst[2][4][4],
                                           const float* Af, const float* Bf,
                                           int wm, int wn, int lane) {
    #pragma unroll
    for (int ks = 0; ks < KC; ks += 8) {
        unsigned bf[4][2];
        #pragma unroll
        for (int nt = 0; nt < 4; nt++) {
            const float* bp = Bf + (wn * 32 + nt * 8 + (lane >> 2)) * AS + ks + (lane & 3);
            bf[nt][0] = __float_as_uint(bp[0]);
            bf[nt][1] = __float_as_uint(bp[4]);
        }
        #pragma unroll
        for (int mt = 0; mt < 2; mt++) {
            const float* ap = Af + (wm * 32 + mt * 16 + (lane >> 2)) * AS + ks + (lane & 3);
            unsigned a0 = __float_as_uint(ap[0]);
            unsigned a2 = __float_as_uint(ap[4]);
            unsigned a1 = __float_as_uint(ap[8 * AS]);
            unsigned a3 = __float_as_uint(ap[8 * AS + 4]);
            #pragma unroll
            for (int nt = 0; nt < 4; nt++)
                mma_tf32(dst[mt][nt], a0, a1, a2, a3, bf[nt][0], bf[nt][1]);
        }
    }
}

// Fused: logits GEMM (tf32 4-pass split, compensated accumulation) + bias +
// softmax + group-limited top-4 routing. One CTA = 64 tokens x 128 experts.
extern "C" __global__ void __launch_bounds__(256, 2)
gate_fused_kernel(const float* __restrict__ x, const float* __restrict__ W,
                  const float* __restrict__ bias, float* __restrict__ out,
                  int out_size, int Ttot)
{
    extern __shared__ float smem[];
    float* A_hi = smem;                  // [64][AS]
    float* A_lo = A_hi + BM * AS;
    float* B_hi = A_lo + BM * AS;        // [128][AS]
    float* B_lo = B_hi + NE * AS;
    float* logits = smem;                // reused after GEMM: [64][LST]

    const int tid  = threadIdx.x;
    const int lane = tid & 31;
    const int warp = tid >> 5;
    const int wm   = warp & 1;           // 2 warps over M (32 rows each)
    const int wn   = warp >> 1;          // 4 warps over N (32 cols each)
    const long tokBase = (long)blockIdx.x * BM;

    // s: compensated hi sum; c: compensation + small-pass sums; w: mma working acc
    float s[2][4][4], c[2][4][4], w[2][4][4];
    #pragma unroll
    for (int i = 0; i < 2; i++)
        #pragma unroll
        for (int j = 0; j < 4; j++)
            #pragma unroll
            for (int k = 0; k < 4; k++) { s[i][j][k] = 0.f; c[i][j][k] = 0.f; w[i][j][k] = 0.f; }

    const int r0 = tid >> 3;             // 0..31 (row group)
    const int f4 = (tid & 7) << 2;       // float4 offset within 32-wide chunk

    for (int kc = 0; kc < DIM; kc += KC) {
        __syncthreads();                 // protect smem from previous iter's reads
        // A tile: 64 rows; B tile: 128 rows. Coalesced LDG.128, split to tf32 hi/lo.
        #pragma unroll
        for (int rr = 0; rr < 2; rr++) {
            int r = r0 + rr * 32;
            float4 v = *(const float4*)(x + (tokBase + r) * DIM + kc + f4);
            float4 h, lo;
            split_tf32(v.x, h.x, lo.x); split_tf32(v.y, h.y, lo.y);
            split_tf32(v.z, h.z, lo.z); split_tf32(v.w, h.w, lo.w);
            *(float4*)(A_hi + r * AS + f4) = h;
            *(float4*)(A_lo + r * AS + f4) = lo;
        }
        #pragma unroll
        for (int rr = 0; rr < 4; rr++) {
            int r = r0 + rr * 32;
            float4 v = *(const float4*)(W + (long)r * DIM + kc + f4);
            float4 h, lo;
            split_tf32(v.x, h.x, lo.x); split_tf32(v.y, h.y, lo.y);
            split_tf32(v.z, h.z, lo.z); split_tf32(v.w, h.w, lo.w);
            *(float4*)(B_hi + r * AS + f4) = h;
            *(float4*)(B_lo + r * AS + f4) = lo;
        }
        __syncthreads();

        // hi*hi pass into w (w==0 at entry), then TwoSum-fold into (s, c)
        pass_chunk(w, A_hi, B_hi, wm, wn, lane);
        #pragma unroll
        for (int mt = 0; mt < 2; mt++)
            #pragma unroll
            for (int nt = 0; nt < 4; nt++)
                #pragma unroll
                for (int k = 0; k < 4; k++) {
                    float p  = w[mt][nt][k];
                    float sv = s[mt][nt][k];
                    float z  = __fadd_rn(sv, p);
                    float t  = __fadd_rn(z, -sv);
                    float e1 = __fadd_rn(p, -t);
                    float t2 = __fadd_rn(z, -t);
                    float e2 = __fadd_rn(sv, -t2);
                    c[mt][nt][k] = __fadd_rn(c[mt][nt][k], __fadd_rn(e1, e2));
                    s[mt][nt][k] = z;
                    w[mt][nt][k] = 0.f;
                }

        // hi*lo + lo*hi + lo*lo passes (small magnitude) into w, fold into c
        pass_chunk(w, A_hi, B_lo, wm, wn, lane);
        pass_chunk(w, A_lo, B_hi, wm, wn, lane);
        pass_chunk(w, A_lo, B_lo, wm, wn, lane);
        #pragma unroll
        for (int mt = 0; mt < 2; mt++)
            #pragma unroll
            for (int nt = 0; nt < 4; nt++)
                #pragma unroll
                for (int k = 0; k < 4; k++) {
                    c[mt][nt][k] = __fadd_rn(c[mt][nt][k], w[mt][nt][k]);
                    w[mt][nt][k] = 0.f;
                }
    }
    __syncthreads();

    // Write logits (+bias) into smem for the fused routing epilogue
    #pragma unroll
    for (int mt = 0; mt < 2; mt++) {
        #pragma unroll
        for (int nt = 0; nt < 4; nt++) {
            int rowb = wm * 32 + mt * 16 + (lane >> 2);
            int colb = wn * 32 + nt * 8 + 2 * (lane & 3);
            float b0v = __ldg(bias + colb), b1v = __ldg(bias + colb + 1);
            #pragma unroll
            for (int half = 0; half < 2; half++) {
                int rw = rowb + half * 8;
                float l0 = __fadd_rn(__fadd_rn(s[mt][nt][2*half],   c[mt][nt][2*half]),   b0v);
                float l1 = __fadd_rn(__fadd_rn(s[mt][nt][2*half+1], c[mt][nt][2*half+1]), b1v);
                logits[rw * LST + colb]     = l0;
                logits[rw * LST + colb + 1] = l1;
            }
        }
    }
    __syncthreads();

    // Routing epilogue: 1 thread per token.
    if (tid < BM) {
        const float* row = logits + tid * LST;
        float v1[2], v2[2];
        #pragma unroll
        for (int g = 0; g < 2; g++) {
            float b1 = -INFINITY, b2 = -INFINITY;
            for (int j = 0; j < 64; j++) {
                float v = row[g * 64 + j];
                if (v > b1) { b2 = b1; b1 = v; } else if (v > b2) { b2 = v; }
            }
            v1[g] = b1; v2[g] = b2;
        }
        float m = fmaxf(v1[0], v1[1]);
        // group representative compare in fp64 (denominator cancels)
        double s0 = exp((double)v1[0] - (double)m) + exp((double)v2[0] - (double)m);
        double s1 = exp((double)v1[1] - (double)m) + exp((double)v2[1] - (double)m);
        int gsel = (s1 > s0) ? 1 : 0;     // tie -> lower group index (matches lax.top_k)
        const float* grow = row + gsel * 64;
        unsigned long long used = 0ull;
        float vals[KSEL]; int ids[KSEL];
        #pragma unroll
        for (int p = 0; p < KSEL; p++) {  // sequential argmax: descending, ties -> lower idx
            float best = -INFINITY; int bi = 0;
            for (int j = 0; j < 64; j++) {
                if (!((used >> j) & 1ull)) {
                    float v = grow[j];
                    if (v > best) { best = v; bi = j; }
                }
            }
            used |= (1ull << bi);
            vals[p] = best; ids[p] = gsel * 64 + bi;
        }
        float e[KSEL], ssum = 0.f;
        #pragma unroll
        for (int p = 0; p < KSEL; p++) { e[p] = expf(vals[p] - m); ssum += e[p]; }
        ssum = fmaxf(ssum, 1e-9f);
        long tok = tokBase + tid;
        #pragma unroll
        for (int p = 0; p < KSEL; p++) out[tok * KSEL + p] = e[p] / ssum;
        if (out_size >= 2 * Ttot * KSEL) {   // [w ; idx] layout: indices as floats
            float* oi = out + (long)Ttot * KSEL;
            #pragma unroll
            for (int p = 0; p < KSEL; p++) oi[tok * KSEL + p] = (float)ids[p];
        }
    }
}

extern "C" void kernel_launch(void* const* d_in, const int* in_sizes, int n_in,
                              void* d_out, int out_size) {
    const float* x    = (const float*)d_in[0];
    const float* W    = (const float*)d_in[1];
    const float* bias = (const float*)d_in[2];
    float* out = (float*)d_out;

    int Ttot = in_sizes[0] / DIM;            // 65536
    int grid = Ttot / BM;                    // 1024
    size_t smem = (size_t)(2 * BM + 2 * NE) * AS * sizeof(float);  // 55296 B

    cudaFuncSetAttribute((const void*)gate_fused_kernel,
                         cudaFuncAttributeMaxDynamicSharedMemorySize, (int)smem);
    gate_fused_kernel<<<grid, 256, smem>>>(x, W, bias, out, out_size, Ttot);
}

// round 3
// speedup vs baseline: 1.5085x; 1.5085x over previous
#include <cuda_runtime.h>
#include <math.h>

#define DIM     2048
#define NE      128
#define KSEL    4
#define BM      128     // tokens per CTA
#define KC      64      // K elems per chunk (8 k-steps of 8)
#define THREADS 512
#define LST     129     // logits smem stride
#define ABLK    33      // padded float4 slots per (rowgroup, kstep) block

// Fragment-major W (hi/lo split), built once per launch by prep kernel.
// Index: ((n8*256 + ksg)*32 + lane), lane = tr*4+tc, element =
//   { Whi[n8*8+tr][ksg*8+tc], Whi[..][..+4], Wlo[..][..], Wlo[..][..+4] }
__device__ float4 g_Wfrag[16 * 256 * 32];   // 2 MB

// Split fp32 into tf32 hi + tf32 lo (x = hi + lo + O(2^-33 x))
__device__ __forceinline__ void split_tf32(float v, float& hi, float& lo) {
    unsigned h, l;
    asm("cvt.rna.tf32.f32 %0, %1;" : "=r"(h) : "f"(v));
    hi = __uint_as_float(h);
    float r = v - hi;
    asm("cvt.rna.tf32.f32 %0, %1;" : "=r"(l) : "f"(r));
    lo = __uint_as_float(l);
}

__device__ __forceinline__ void mma_tf32(float c[4],
                                         unsigned a0, unsigned a1, unsigned a2, unsigned a3,
                                         unsigned b0, unsigned b1) {
    asm volatile(
        "mma.sync.aligned.m16n8k8.row.col.f32.tf32.tf32.f32 "
        "{%0,%1,%2,%3}, {%4,%5,%6,%7}, {%8,%9}, {%0,%1,%2,%3};\n"
        : "+f"(c[0]), "+f"(c[1]), "+f"(c[2]), "+f"(c[3])
        : "r"(a0), "r"(a1), "r"(a2), "r"(a3), "r"(b0), "r"(b1));
}

// One-time (per launch) W -> fragment-major hi/lo split
extern "C" __global__ void prep_wfrag_kernel(const float* __restrict__ W) {
    int t    = blockIdx.x * 256 + threadIdx.x;   // 0..131071
    int lane = t & 31;
    int ksg  = (t >> 5) & 255;
    int n8   = t >> 13;
    int r = n8 * 8 + (lane >> 2);
    int c = ksg * 8 + (lane & 3);
    float w0 = W[r * DIM + c];
    float w1 = W[r * DIM + c + 4];
    float h0, l0, h1, l1;
    split_tf32(w0, h0, l0);
    split_tf32(w1, h1, l1);
    g_Wfrag[t] = make_float4(h0, h1, l0, l1);
}

// Fused: tf32 4-product compensated GEMM + bias + softmax + group-limited top-4.
// One CTA = 128 tokens x 128 experts. A staged in fragment-major smem; B direct
// from g_Wfrag (L2-resident). 16 warps: wm = warp&3 (32 rows), wn = warp>>2 (32 experts).
extern "C" __global__ void __launch_bounds__(THREADS, 1)
gate_fused_kernel(const float* __restrict__ x, const float* __restrict__ bias,
                  float* __restrict__ out, int out_size, int Ttot)
{
    extern __shared__ float smem[];
    float4* Asm   = (float4*)smem;   // [16 rg][8 ks][ABLK] float4, swizzled
    float* logits = smem;            // reused after GEMM: [128][LST]

    const int tid  = threadIdx.x;
    const int lane = tid & 31;
    const int warp = tid >> 5;
    const int wm   = warp & 3;       // 4 M groups of 32 rows
    const int wn   = warp >> 2;      // 4 N groups of 32 experts
    const long tokBase = (long)blockIdx.x * BM;

    // s: compensated hi sum; c: compensation + small products; w: hh working acc
    float s[2][4][4], c[2][4][4], w[2][4][4];
    #pragma unroll
    for (int i = 0; i < 2; i++)
        #pragma unroll
        for (int j = 0; j < 4; j++)
            #pragma unroll
            for (int k = 0; k < 4; k++) { s[i][j][k] = 0.f; c[i][j][k] = 0.f; w[i][j][k] = 0.f; }

    for (int kc = 0; kc < DIM; kc += KC) {
        __syncthreads();
        // Producer: stage A chunk (128 rows x 64 cols) in fragment-major hi/lo float4s.
        #pragma unroll
        for (int it = 0; it < 2; it++) {
            int linear = it * THREADS + tid;   // 0..1023 = (row, ks)
            int row = linear >> 3;
            int ks  = linear & 7;
            const float* xp = x + (tokBase + row) * DIM + kc + ks * 8;
            float4 va = *(const float4*)xp;
            float4 vb = *(const float4*)(xp + 4);
            float ha[4], la[4], hb[4], lb[4];
            split_tf32(va.x, ha[0], la[0]); split_tf32(va.y, ha[1], la[1]);
            split_tf32(va.z, ha[2], la[2]); split_tf32(va.w, ha[3], la[3]);
            split_tf32(vb.x, hb[0], lb[0]); split_tf32(vb.y, hb[1], lb[1]);
            split_tf32(vb.z, hb[2], lb[2]); split_tf32(vb.w, hb[3], lb[3]);
            int rg = row >> 3, tr = row & 7;
            int base = (rg * 8 + ks) * ABLK + ((tr + ks) & 7) * 4;  // rotation swizzle
            #pragma unroll
            for (int tc = 0; tc < 4; tc++)
                Asm[base + tc] = make_float4(ha[tc], hb[tc], la[tc], lb[tc]);
        }
        __syncthreads();

        const int ksg0 = kc >> 3;
        #pragma unroll
        for (int ks = 0; ks < 8; ks++) {
            // A fragments: 2 LDS.128 per mt ({hi(c),hi(c+4),lo(c),lo(c+4)} rows r, r+8)
            float4 af0[2], af1[2];
            const int li = (((lane >> 2) + ks) & 7) * 4 + (lane & 3);
            #pragma unroll
            for (int mt = 0; mt < 2; mt++) {
                int rg = wm * 4 + mt * 2;
                af0[mt] = Asm[(rg * 8 + ks) * ABLK + li];
                af1[mt] = Asm[((rg + 1) * 8 + ks) * ABLK + li];
            }
            #pragma unroll
            for (int nt = 0; nt < 4; nt++) {
                int n8 = wn * 4 + nt;
                float4 bf = g_Wfrag[(n8 * 256 + ksg0 + ks) * 32 + lane];
                unsigned b0h = __float_as_uint(bf.x), b1h = __float_as_uint(bf.y);
                unsigned b0l = __float_as_uint(bf.z), b1l = __float_as_uint(bf.w);
                #pragma unroll
                for (int mt = 0; mt < 2; mt++) {
                    unsigned a0h = __float_as_uint(af0[mt].x), a2h = __float_as_uint(af0[mt].y);
                    unsigned a0l = __float_as_uint(af0[mt].z), a2l = __float_as_uint(af0[mt].w);
                    unsigned a1h = __float_as_uint(af1[mt].x), a3h = __float_as_uint(af1[mt].y);
                    unsigned a1l = __float_as_uint(af1[mt].z), a3l = __float_as_uint(af1[mt].w);
                    mma_tf32(w[mt][nt], a0h, a1h, a2h, a3h, b0h, b1h);  // hh
                    mma_tf32(c[mt][nt], a0h, a1h, a2h, a3h, b0l, b1l);  // hl
                    mma_tf32(c[mt][nt], a0l, a1l, a2l, a3l, b0h, b1h);  // lh
                    mma_tf32(c[mt][nt], a0l, a1l, a2l, a3l, b0l, b1l);  // ll
                }
            }
        }

        // TwoSum-fold the chunk's hh partial into (s, c); reset w.
        #pragma unroll
        for (int mt = 0; mt < 2; mt++)
            #pragma unroll
            for (int nt = 0; nt < 4; nt++)
                #pragma unroll
                for (int k = 0; k < 4; k++) {
                    float p  = w[mt][nt][k];
                    float sv = s[mt][nt][k];
                    float z  = __fadd_rn(sv, p);
                    float t  = __fadd_rn(z, -sv);
                    float e1 = __fadd_rn(p, -t);
                    float t2 = __fadd_rn(z, -t);
                    float e2 = __fadd_rn(sv, -t2);
                    c[mt][nt][k] = __fadd_rn(c[mt][nt][k], __fadd_rn(e1, e2));
                    s[mt][nt][k] = z;
                    w[mt][nt][k] = 0.f;
                }
    }
    __syncthreads();

    // Write logits (+bias) into smem for the fused routing epilogue
    #pragma unroll
    for (int mt = 0; mt < 2; mt++) {
        #pragma unroll
        for (int nt = 0; nt < 4; nt++) {
            int rowb = wm * 32 + mt * 16 + (lane >> 2);
            int colb = wn * 32 + nt * 8 + 2 * (lane & 3);
            float b0v = __ldg(bias + colb), b1v = __ldg(bias + colb + 1);
            #pragma unroll
            for (int half = 0; half < 2; half++) {
                int rw = rowb + half * 8;
                float l0 = __fadd_rn(__fadd_rn(s[mt][nt][2*half],   c[mt][nt][2*half]),   b0v);
                float l1 = __fadd_rn(__fadd_rn(s[mt][nt][2*half+1], c[mt][nt][2*half+1]), b1v);
                logits[rw * LST + colb]     = l0;
                logits[rw * LST + colb + 1] = l1;
            }
        }
    }
    __syncthreads();

    // Routing epilogue: 1 thread per token.
    if (tid < BM) {
        const float* row = logits + tid * LST;
        float v1[2], v2[2];
        #pragma unroll
        for (int g = 0; g < 2; g++) {
            float b1 = -INFINITY, b2 = -INFINITY;
            for (int j = 0; j < 64; j++) {
                float v = row[g * 64 + j];
                if (v > b1) { b2 = b1; b1 = v; } else if (v > b2) { b2 = v; }
            }
            v1[g] = b1; v2[g] = b2;
        }
        float m = fmaxf(v1[0], v1[1]);
        // group representative compare in fp64 (softmax denominator cancels)
        double s0 = exp((double)v1[0] - (double)m) + exp((double)v2[0] - (double)m);
        double s1 = exp((double)v1[1] - (double)m) + exp((double)v2[1] - (double)m);
        int gsel = (s1 > s0) ? 1 : 0;     // tie -> lower group index (matches lax.top_k)
        const float* grow = row + gsel * 64;
        unsigned long long used = 0ull;
        float vals[KSEL]; int ids[KSEL];
        #pragma unroll
        for (int p = 0; p < KSEL; p++) {  // sequential argmax: descending, ties -> lower idx
            float best = -INFINITY; int bi = 0;
            for (int j = 0; j < 64; j++) {
                if (!((used >> j) & 1ull)) {
                    float v = grow[j];
                    if (v > best) { best = v; bi = j; }
                }
            }
            used |= (1ull << bi);
            vals[p] = best; ids[p] = gsel * 64 + bi;
        }
        float e[KSEL], ssum = 0.f;
        #pragma unroll
        for (int p = 0; p < KSEL; p++) { e[p] = expf(vals[p] - m); ssum += e[p]; }
        ssum = fmaxf(ssum, 1e-9f);
        long tok = tokBase + tid;
        #pragma unroll
        for (int p = 0; p < KSEL; p++) out[tok * KSEL + p] = e[p] / ssum;
        if (out_size >= 2 * Ttot * KSEL) {   // [w ; idx] layout: indices as floats
            float* oi = out + (long)Ttot * KSEL;
            #pragma unroll
            for (int p = 0; p < KSEL; p++) oi[tok * KSEL + p] = (float)ids[p];
        }
    }
}

extern "C" void kernel_launch(void* const* d_in, const int* in_sizes, int n_in,
                              void* d_out, int out_size) {
    const float* x    = (const float*)d_in[0];
    const float* W    = (const float*)d_in[1];
    const float* bias = (const float*)d_in[2];
    float* out = (float*)d_out;

    int Ttot = in_sizes[0] / DIM;                 // 65536
    int grid = Ttot / BM;                         // 512
    size_t smem = (size_t)(16 * 8 * ABLK) * sizeof(float4);   // 67584 B (>= logits 66048)

    cudaFuncSetAttribute((const void*)gate_fused_kernel,
                         cudaFuncAttributeMaxDynamicSharedMemorySize, (int)smem);

    prep_wfrag_kernel<<<512, 256>>>(W);
    gate_fused_kernel<<<grid, THREADS, smem>>>(x, bias, out, out_size, Ttot);
}

// round 5
// speedup vs baseline: 1.6922x; 1.1217x over previous
#include <cuda_runtime.h>
#include <math.h>
#include <stdint.h>

#define DIM     2048
#define NE      128
#define KSEL    4
#define BM      128     // tokens per CTA
#define KC      64      // K elems per chunk (8 k-steps of 8)
#define NCHUNK  (DIM/KC)
#define THREADS 512
#define LST     129     // logits smem stride
#define ABLK    33      // padded float4 slots per (rowgroup, kstep) block
#define BUFSZ   (16 * 8 * ABLK * 16)          // one A staging buffer, bytes (67584)
#define SOFF    (2 * BUFSZ)                   // s-array offset in smem
#define SMEM_TOTAL (SOFF + 32 * THREADS * 4)  // 200704 B

// Fragment-major W (hi/lo split), built once per launch by prep kernel.
// g_Wfrag[(n8*256 + ksg)*32 + lane] = {Whi[n8*8+tr][ksg*8+tc], Whi[..][..+4],
//                                      Wlo[..][..],            Wlo[..][..+4]}, lane=tr*4+tc
__device__ float4 g_Wfrag[16 * 256 * 32];   // 2 MB

// Split fp32 into tf32 hi + tf32 lo (x = hi + lo + O(2^-33 x))
__device__ __forceinline__ void split_tf32(float v, float& hi, float& lo) {
    unsigned h, l;
    asm("cvt.rna.tf32.f32 %0, %1;" : "=r"(h) : "f"(v));
    hi = __uint_as_float(h);
    float r = v - hi;
    asm("cvt.rna.tf32.f32 %0, %1;" : "=r"(l) : "f"(r));
    lo = __uint_as_float(l);
}

__device__ __forceinline__ void mma_tf32(float c[4],
                                         unsigned a0, unsigned a1, unsigned a2, unsigned a3,
                                         unsigned b0, unsigned b1) {
    asm volatile(
        "mma.sync.aligned.m16n8k8.row.col.f32.tf32.tf32.f32 "
        "{%0,%1,%2,%3}, {%4,%5,%6,%7}, {%8,%9}, {%0,%1,%2,%3};\n"
        : "+f"(c[0]), "+f"(c[1]), "+f"(c[2]), "+f"(c[3])
        : "r"(a0), "r"(a1), "r"(a2), "r"(a3), "r"(b0), "r"(b1));
}

// One-time (per launch) W -> fragment-major hi/lo split
extern "C" __global__ void prep_wfrag_kernel(const float* __restrict__ W) {
    int t    = blockIdx.x * 256 + threadIdx.x;   // 0..131071
    int lane = t & 31;
    int ksg  = (t >> 5) & 255;
    int n8   = t >> 13;
    int r = n8 * 8 + (lane >> 2);
    int c = ksg * 8 + (lane & 3);
    float w0 = W[r * DIM + c];
    float w1 = W[r * DIM + c + 4];
    float h0, l0, h1, l1;
    split_tf32(w0, h0, l0);
    split_tf32(w1, l1, l1);   // placeholder overwritten below (keep regs simple)
    split_tf32(w1, h1, l1);
    g_Wfrag[t] = make_float4(h0, h1, l0, l1);
}

// Stage one A chunk (128 rows x 64 cols) into fragment-major hi/lo float4s.
__device__ __forceinline__ void stage_chunk(float4* Asm, const float* __restrict__ x,
                                            long tokBase, int kc, int tid) {
    #pragma unroll
    for (int it = 0; it < 2; it++) {
        int linear = it * THREADS + tid;   // 0..1023 = (row, ks)
        int row = linear >> 3;
        int ks  = linear & 7;
        const float* xp = x + (tokBase + row) * DIM + kc + ks * 8;
        float4 va = *(const float4*)xp;
        float4 vb = *(const float4*)(xp + 4);
        float ha[4], la[4], hb[4], lb[4];
        split_tf32(va.x, ha[0], la[0]); split_tf32(va.y, ha[1], la[1]);
        split_tf32(va.z, ha[2], la[2]); split_tf32(va.w, ha[3], la[3]);
        split_tf32(vb.x, hb[0], lb[0]); split_tf32(vb.y, hb[1], lb[1]);
        split_tf32(vb.z, hb[2], lb[2]); split_tf32(vb.w, hb[3], lb[3]);
        int rg = row >> 3, tr = row & 7;
        int base = (rg * 8 + ks) * ABLK + ((tr + ks) & 7) * 4;  // rotation swizzle
        #pragma unroll
        for (int tc = 0; tc < 4; tc++)
            Asm[base + tc] = make_float4(ha[tc], hb[tc], la[tc], lb[tc]);
    }
}

// Fused: tf32 4-product compensated GEMM + bias + softmax + group-limited top-4.
// One CTA = 128 tokens x 128 experts. A double-buffered in fragment-major smem;
// B direct from g_Wfrag (L2-resident). 16 warps: wm = warp&3, wn = warp>>2.
extern "C" __global__ void __launch_bounds__(THREADS, 1)
gate_fused_kernel(const float* __restrict__ x, const float* __restrict__ bias,
                  float* __restrict__ out, int out_size, int Ttot)
{
    extern __shared__ char smem[];
    float* s_sm   = (float*)(smem + SOFF);   // TwoSum high parts: [32][THREADS]
    float* logits = (float*)smem;            // reused after GEMM: [128][LST]

    const int tid  = threadIdx.x;
    const int lane = tid & 31;
    const int warp = tid >> 5;
    const int wm   = warp & 3;       // 4 M groups of 32 rows
    const int wn   = warp >> 2;      // 4 N groups of 32 experts
    const long tokBase = (long)blockIdx.x * BM;

    // w: hh mma accumulator (windowed, 4 chunks); c: compensation + small products
    float w[2][4][4], c[2][4][4];
    #pragma unroll
    for (int i = 0; i < 2; i++)
        #pragma unroll
        for (int j = 0; j < 4; j++)
            #pragma unroll
            for (int k = 0; k < 4; k++) { w[i][j][k] = 0.f; c[i][j][k] = 0.f; }
    #pragma unroll
    for (int j = 0; j < 32; j++) s_sm[j * THREADS + tid] = 0.f;

    stage_chunk((float4*)smem, x, tokBase, 0, tid);
    __syncthreads();

    for (int i = 0; i < NCHUNK; i++) {
        // Stage next chunk first (overlaps LDG+split with this chunk's mma)
        if (i + 1 < NCHUNK)
            stage_chunk((float4*)(smem + ((i + 1) & 1) * BUFSZ), x, tokBase, (i + 1) * KC, tid);

        const float4* Asm = (const float4*)(smem + (i & 1) * BUFSZ);
        const int ksg0 = i * 8;
        #pragma unroll
        for (int ks = 0; ks < 8; ks++) {
            // All 4 B fragments up front (MLP=4 over the L2-latency LDGs)
            float4 bf[4];
            #pragma unroll
            for (int nt = 0; nt < 4; nt++)
                bf[nt] = g_Wfrag[((wn * 4 + nt) * 256 + ksg0 + ks) * 32 + lane];
            // A fragments: 2 LDS.128 per mt
            float4 af0[2], af1[2];
            const int li = (((lane >> 2) + ks) & 7) * 4 + (lane & 3);
            #pragma unroll
            for (int mt = 0; mt < 2; mt++) {
                int rg = wm * 4 + mt * 2;
                af0[mt] = Asm[(rg * 8 + ks) * ABLK + li];
                af1[mt] = Asm[((rg + 1) * 8 + ks) * ABLK + li];
            }
            #pragma unroll
            for (int nt = 0; nt < 4; nt++) {
                unsigned b0h = __float_as_uint(bf[nt].x), b1h = __float_as_uint(bf[nt].y);
                unsigned b0l = __float_as_uint(bf[nt].z), b1l = __float_as_uint(bf[nt].w);
                #pragma unroll
                for (int mt = 0; mt < 2; mt++) {
                    unsigned a0h = __float_as_uint(af0[mt].x), a2h = __float_as_uint(af0[mt].y);
                    unsigned a0l = __float_as_uint(af0[mt].z), a2l = __float_as_uint(af0[mt].w);
                    unsigned a1h = __float_as_uint(af1[mt].x), a3h = __float_as_uint(af1[mt].y);
                    unsigned a1l = __float_as_uint(af1[mt].z), a3l = __float_as_uint(af1[mt].w);
                    mma_tf32(w[mt][nt], a0h, a1h, a2h, a3h, b0h, b1h);  // hh
                    mma_tf32(c[mt][nt], a0h, a1h, a2h, a3h, b0l, b1l);  // hl
                    mma_tf32(c[mt][nt], a0l, a1l, a2l, a3l, b0h, b1h);  // lh
                    mma_tf32(c[mt][nt], a0l, a1l, a2l, a3l, b0l, b1l);  // ll
                }
            }
        }

        // Every 4 chunks: TwoSum-fold the hh window into (s_sm, c); reset w.
        if ((i & 3) == 3) {
            #pragma unroll
            for (int mt = 0; mt < 2; mt++)
                #pragma unroll
                for (int nt = 0; nt < 4; nt++)
                    #pragma unroll
                    for (int k = 0; k < 4; k++) {
                        int j = ((mt * 4 + nt) * 4 + k);
                        float p  = w[mt][nt][k];
                        float sv = s_sm[j * THREADS + tid];
                        float z  = __fadd_rn(sv, p);
                        float t  = __fadd_rn(z, -sv);
                        float e1 = __fadd_rn(p, -t);
                        float t2 = __fadd_rn(z, -t);
                        float e2 = __fadd_rn(sv, -t2);
                        c[mt][nt][k] = __fadd_rn(c[mt][nt][k], __fadd_rn(e1, e2));
                        s_sm[j * THREADS + tid] = z;
                        w[mt][nt][k] = 0.f;
                    }
        }
        __syncthreads();   // all reads of buf[i&1] done; buf[(i+1)&1] fully staged
    }

    // Write logits (+bias) into smem for the fused routing epilogue
    #pragma unroll
    for (int mt = 0; mt < 2; mt++) {
        #pragma unroll
        for (int nt = 0; nt < 4; nt++) {
            int rowb = wm * 32 + mt * 16 + (lane >> 2);
            int colb = wn * 32 + nt * 8 + 2 * (lane & 3);
            float b0v = __ldg(bias + colb), b1v = __ldg(bias + colb + 1);
            #pragma unroll
            for (int half = 0; half < 2; half++) {
                int rw = rowb + half * 8;
                int j0 = ((mt * 4 + nt) * 4 + 2 * half);
                float s0 = s_sm[j0 * THREADS + tid];
                float s1 = s_sm[(j0 + 1) * THREADS + tid];
                float l0 = __fadd_rn(__fadd_rn(s0, c[mt][nt][2*half]),   b0v);
                float l1 = __fadd_rn(__fadd_rn(s1, c[mt][nt][2*half+1]), b1v);
                logits[rw * LST + colb]     = l0;
                logits[rw * LST + colb + 1] = l1;
            }
        }
    }
    __syncthreads();

    // Routing epilogue: 1 thread per token (identical to passing round-2/3 logic)
    if (tid < BM) {
        const float* row = logits + tid * LST;
        float v1[2], v2[2];
        #pragma unroll
        for (int g = 0; g < 2; g++) {
            float b1 = -INFINITY, b2 = -INFINITY;
            for (int j = 0; j < 64; j++) {
                float v = row[g * 64 + j];
                if (v > b1) { b2 = b1; b1 = v; } else if (v > b2) { b2 = v; }
            }
            v1[g] = b1; v2[g] = b2;
        }
        float m = fmaxf(v1[0], v1[1]);
        double s0 = exp((double)v1[0] - (double)m) + exp((double)v2[0] - (double)m);
        double s1 = exp((double)v1[1] - (double)m) + exp((double)v2[1] - (double)m);
        int gsel = (s1 > s0) ? 1 : 0;     // tie -> lower group index (matches lax.top_k)
        const float* grow = row + gsel * 64;
        unsigned long long used = 0ull;
        float vals[KSEL]; int ids[KSEL];
        #pragma unroll
        for (int p = 0; p < KSEL; p++) {  // sequential argmax: descending, ties -> lower idx
            float best = -INFINITY; int bi = 0;
            for (int j = 0; j < 64; j++) {
                if (!((used >> j) & 1ull)) {
                    float v = grow[j];
                    if (v > best) { best = v; bi = j; }
                }
            }
            used |= (1ull << bi);
            vals[p] = best; ids[p] = gsel * 64 + bi;
        }
        float e[KSEL], ssum = 0.f;
        #pragma unroll
        for (int p = 0; p < KSEL; p++) { e[p] = expf(vals[p] - m); ssum += e[p]; }
        ssum = fmaxf(ssum, 1e-9f);
        long tok = tokBase + tid;
        #pragma unroll
        for (int p = 0; p < KSEL; p++) out[tok * KSEL + p] = e[p] / ssum;
        if (out_size >= 2 * Ttot * KSEL) {   // [w ; idx] layout: indices as floats
            float* oi = out + (long)Ttot * KSEL;
            #pragma unroll
            for (int p = 0; p < KSEL; p++) oi[tok * KSEL + p] = (float)ids[p];
        }
    }
}

extern "C" void kernel_launch(void* const* d_in, const int* in_sizes, int n_in,
                              void* d_out, int out_size) {
    const float* x    = (const float*)d_in[0];
    const float* W    = (const float*)d_in[1];
    const float* bias = (const float*)d_in[2];
    float* out = (float*)d_out;

    int Ttot = in_sizes[0] / DIM;   // 65536
    int grid = Ttot / BM;           // 512

    cudaFuncSetAttribute((const void*)gate_fused_kernel,
                         cudaFuncAttributeMaxDynamicSharedMemorySize, SMEM_TOTAL);

    prep_wfrag_kernel<<<512, 256>>>(W);
    gate_fused_kernel<<<grid, THREADS, SMEM_TOTAL>>>(x, bias, out, out_size, Ttot);
}

// round 6
// speedup vs baseline: 2.0243x; 1.1963x over previous
#include <cuda_runtime.h>
#include <math.h>
#include <stdint.h>

#define DIM     2048
#define NE      128
#define KSEL    4
#define BM      128     // tokens per CTA
#define KC      64      // K elems per chunk (8 k-steps of 8)
#define NCHUNK  (DIM/KC)
#define THREADS 512
#define LST     129     // logits smem stride
#define ABLK    33      // padded float4 slots per (rowgroup, kstep) block
#define BUFSZ   (16 * 8 * ABLK * 16)          // one A staging buffer, bytes (67584)
#define SOFF    (2 * BUFSZ)                   // s-array offset in smem
#define SMEM_TOTAL (SOFF + 32 * THREADS * 4)  // 200704 B

// Fragment-major W (hi/lo split), built once per launch by prep kernel.
// g_Wfrag[(n8*256 + ksg)*32 + lane] = {Whi[n8*8+tr][ksg*8+tc], Whi[..][..+4],
//                                      Wlo[..][..],            Wlo[..][..+4]}, lane=tr*4+tc
__device__ float4 g_Wfrag[16 * 256 * 32];   // 2 MB

// Split fp32 into tf32 hi + tf32 lo (x = hi + lo + O(2^-33 x))
__device__ __forceinline__ void split_tf32(float v, float& hi, float& lo) {
    unsigned h, l;
    asm("cvt.rna.tf32.f32 %0, %1;" : "=r"(h) : "f"(v));
    hi = __uint_as_float(h);
    float r = v - hi;
    asm("cvt.rna.tf32.f32 %0, %1;" : "=r"(l) : "f"(r));
    lo = __uint_as_float(l);
}

__device__ __forceinline__ void mma_tf32(float c[4],
                                         unsigned a0, unsigned a1, unsigned a2, unsigned a3,
                                         unsigned b0, unsigned b1) {
    asm volatile(
        "mma.sync.aligned.m16n8k8.row.col.f32.tf32.tf32.f32 "
        "{%0,%1,%2,%3}, {%4,%5,%6,%7}, {%8,%9}, {%0,%1,%2,%3};\n"
        : "+f"(c[0]), "+f"(c[1]), "+f"(c[2]), "+f"(c[3])
        : "r"(a0), "r"(a1), "r"(a2), "r"(a3), "r"(b0), "r"(b1));
}

// One-time (per launch) W -> fragment-major hi/lo split
extern "C" __global__ void prep_wfrag_kernel(const float* __restrict__ W) {
    int t    = blockIdx.x * 256 + threadIdx.x;   // 0..131071
    int lane = t & 31;
    int ksg  = (t >> 5) & 255;
    int n8   = t >> 13;
    int r = n8 * 8 + (lane >> 2);
    int c = ksg * 8 + (lane & 3);
    float w0 = W[r * DIM + c];
    float w1 = W[r * DIM + c + 4];
    float h0, l0, h1, l1;
    split_tf32(w0, h0, l0);
    split_tf32(w1, h1, l1);
    g_Wfrag[t] = make_float4(h0, h1, l0, l1);
}

// Stage one A chunk (128 rows x 64 cols) into fragment-major hi/lo float4s.
__device__ __forceinline__ void stage_chunk(float4* Asm, const float* __restrict__ x,
                                            long tokBase, int kc, int tid) {
    #pragma unroll
    for (int it = 0; it < 2; it++) {
        int linear = it * THREADS + tid;   // 0..1023 = (row, ks)
        int row = linear >> 3;
        int ks  = linear & 7;
        const float* xp = x + (tokBase + row) * DIM + kc + ks * 8;
        float4 va = *(const float4*)xp;
        float4 vb = *(const float4*)(xp + 4);
        float ha[4], la[4], hb[4], lb[4];
        split_tf32(va.x, ha[0], la[0]); split_tf32(va.y, ha[1], la[1]);
        split_tf32(va.z, ha[2], la[2]); split_tf32(va.w, ha[3], la[3]);
        split_tf32(vb.x, hb[0], lb[0]); split_tf32(vb.y, hb[1], lb[1]);
        split_tf32(vb.z, hb[2], lb[2]); split_tf32(vb.w, hb[3], lb[3]);
        int rg = row >> 3, tr = row & 7;
        int base = (rg * 8 + ks) * ABLK + ((tr + ks) & 7) * 4;  // rotation swizzle
        #pragma unroll
        for (int tc = 0; tc < 4; tc++)
            Asm[base + tc] = make_float4(ha[tc], hb[tc], la[tc], lb[tc]);
    }
}

// Fused: tf32 3-product compensated GEMM (hh + hl + lh; ll term ~1e-7, dropped)
// + bias + softmax + group-limited top-4. One CTA = 128 tokens x 128 experts.
// A double-buffered fragment-major smem; B direct from g_Wfrag (L2-resident).
extern "C" __global__ void __launch_bounds__(THREADS, 1)
gate_fused_kernel(const float* __restrict__ x, const float* __restrict__ bias,
                  float* __restrict__ out, int out_size, int Ttot)
{
    extern __shared__ char smem[];
    float* s_sm   = (float*)(smem + SOFF);   // TwoSum high parts: [32][THREADS]
    float* logits = (float*)smem;            // reused after GEMM: [128][LST]

    const int tid  = threadIdx.x;
    const int lane = tid & 31;
    const int warp = tid >> 5;
    const int wm   = warp & 3;       // 4 M groups of 32 rows
    const int wn   = warp >> 2;      // 4 N groups of 32 experts
    const long tokBase = (long)blockIdx.x * BM;

    // w: hh mma accumulator (windowed, 4 chunks); c: compensation + small products
    float w[2][4][4], c[2][4][4];
    #pragma unroll
    for (int i = 0; i < 2; i++)
        #pragma unroll
        for (int j = 0; j < 4; j++)
            #pragma unroll
            for (int k = 0; k < 4; k++) { w[i][j][k] = 0.f; c[i][j][k] = 0.f; }
    #pragma unroll
    for (int j = 0; j < 32; j++) s_sm[j * THREADS + tid] = 0.f;

    stage_chunk((float4*)smem, x, tokBase, 0, tid);
    __syncthreads();

    for (int i = 0; i < NCHUNK; i++) {
        // Stage next chunk first (overlaps LDG+split with this chunk's mma)
        if (i + 1 < NCHUNK)
            stage_chunk((float4*)(smem + ((i + 1) & 1) * BUFSZ), x, tokBase, (i + 1) * KC, tid);

        const float4* Asm = (const float4*)(smem + (i & 1) * BUFSZ);
        const int ksg0 = i * 8;
        #pragma unroll
        for (int ks = 0; ks < 8; ks++) {
            // All 4 B fragments up front (MLP=4 over the L2-latency LDGs)
            float4 bf[4];
            #pragma unroll
            for (int nt = 0; nt < 4; nt++)
                bf[nt] = g_Wfrag[((wn * 4 + nt) * 256 + ksg0 + ks) * 32 + lane];
            // A fragments: 2 LDS.128 per mt
            float4 af0[2], af1[2];
            const int li = (((lane >> 2) + ks) & 7) * 4 + (lane & 3);
            #pragma unroll
            for (int mt = 0; mt < 2; mt++) {
                int rg = wm * 4 + mt * 2;
                af0[mt] = Asm[(rg * 8 + ks) * ABLK + li];
                af1[mt] = Asm[((rg + 1) * 8 + ks) * ABLK + li];
            }
            #pragma unroll
            for (int nt = 0; nt < 4; nt++) {
                unsigned b0h = __float_as_uint(bf[nt].x), b1h = __float_as_uint(bf[nt].y);
                unsigned b0l = __float_as_uint(bf[nt].z), b1l = __float_as_uint(bf[nt].w);
                #pragma unroll
                for (int mt = 0; mt < 2; mt++) {
                    unsigned a0h = __float_as_uint(af0[mt].x), a2h = __float_as_uint(af0[mt].y);
                    unsigned a0l = __float_as_uint(af0[mt].z), a2l = __float_as_uint(af0[mt].w);
                    unsigned a1h = __float_as_uint(af1[mt].x), a3h = __float_as_uint(af1[mt].y);
                    unsigned a1l = __float_as_uint(af1[mt].z), a3l = __float_as_uint(af1[mt].w);
                    mma_tf32(w[mt][nt], a0h, a1h, a2h, a3h, b0h, b1h);  // hh
                    mma_tf32(c[mt][nt], a0h, a1h, a2h, a3h, b0l, b1l);  // hl
                    mma_tf32(c[mt][nt], a0l, a1l, a2l, a3l, b0h, b1h);  // lh
                }
            }
        }

        // Every 4 chunks: TwoSum-fold the hh window into (s_sm, c); reset w.
        if ((i & 3) == 3) {
            #pragma unroll
            for (int mt = 0; mt < 2; mt++)
                #pragma unroll
                for (int nt = 0; nt < 4; nt++)
                    #pragma unroll
                    for (int k = 0; k < 4; k++) {
                        int j = ((mt * 4 + nt) * 4 + k);
                        float p  = w[mt][nt][k];
                        float sv = s_sm[j * THREADS + tid];
                        float z  = __fadd_rn(sv, p);
                        float t  = __fadd_rn(z, -sv);
                        float e1 = __fadd_rn(p, -t);
                        float t2 = __fadd_rn(z, -t);
                        float e2 = __fadd_rn(sv, -t2);
                        c[mt][nt][k] = __fadd_rn(c[mt][nt][k], __fadd_rn(e1, e2));
                        s_sm[j * THREADS + tid] = z;
                        w[mt][nt][k] = 0.f;
                    }
        }
        __syncthreads();   // all reads of buf[i&1] done; buf[(i+1)&1] fully staged
    }

    // Write logits (+bias) into smem for the fused routing epilogue
    #pragma unroll
    for (int mt = 0; mt < 2; mt++) {
        #pragma unroll
        for (int nt = 0; nt < 4; nt++) {
            int rowb = wm * 32 + mt * 16 + (lane >> 2);
            int colb = wn * 32 + nt * 8 + 2 * (lane & 3);
            float b0v = __ldg(bias + colb), b1v = __ldg(bias + colb + 1);
            #pragma unroll
            for (int half = 0; half < 2; half++) {
                int rw = rowb + half * 8;
                int j0 = ((mt * 4 + nt) * 4 + 2 * half);
                float s0 = s_sm[j0 * THREADS + tid];
                float s1 = s_sm[(j0 + 1) * THREADS + tid];
                float l0 = __fadd_rn(__fadd_rn(s0, c[mt][nt][2*half]),   b0v);
                float l1 = __fadd_rn(__fadd_rn(s1, c[mt][nt][2*half+1]), b1v);
                logits[rw * LST + colb]     = l0;
                logits[rw * LST + colb + 1] = l1;
            }
        }
    }
    __syncthreads();

    // Routing epilogue: 1 thread per token (identical to passing round-2/3/5 logic)
    if (tid < BM) {
        const float* row = logits + tid * LST;
        float v1[2], v2[2];
        #pragma unroll
        for (int g = 0; g < 2; g++) {
            float b1 = -INFINITY, b2 = -INFINITY;
            for (int j = 0; j < 64; j++) {
                float v = row[g * 64 + j];
                if (v > b1) { b2 = b1; b1 = v; } else if (v > b2) { b2 = v; }
            }
            v1[g] = b1; v2[g] = b2;
        }
        float m = fmaxf(v1[0], v1[1]);
        double s0 = exp((double)v1[0] - (double)m) + exp((double)v2[0] - (double)m);
        double s1 = exp((double)v1[1] - (double)m) + exp((double)v2[1] - (double)m);
        int gsel = (s1 > s0) ? 1 : 0;     // tie -> lower group index (matches lax.top_k)
        const float* grow = row + gsel * 64;
        unsigned long long used = 0ull;
        float vals[KSEL]; int ids[KSEL];
        #pragma unroll
        for (int p = 0; p < KSEL; p++) {  // sequential argmax: descending, ties -> lower idx
            float best = -INFINITY; int bi = 0;
            for (int j = 0; j < 64; j++) {
                if (!((used >> j) & 1ull)) {
                    float v = grow[j];
                    if (v > best) { best = v; bi = j; }
                }
            }
            used |= (1ull << bi);
            vals[p] = best; ids[p] = gsel * 64 + bi;
        }
        float e[KSEL], ssum = 0.f;
        #pragma unroll
        for (int p = 0; p < KSEL; p++) { e[p] = expf(vals[p] - m); ssum += e[p]; }
        ssum = fmaxf(ssum, 1e-9f);
        long tok = tokBase + tid;
        #pragma unroll
        for (int p = 0; p < KSEL; p++) out[tok * KSEL + p] = e[p] / ssum;
        if (out_size >= 2 * Ttot * KSEL) {   // [w ; idx] layout: indices as floats
            float* oi = out + (long)Ttot * KSEL;
            #pragma unroll
            for (int p = 0; p < KSEL; p++) oi[tok * KSEL + p] = (float)ids[p];
        }
    }
}

extern "C" void kernel_launch(void* const* d_in, const int* in_sizes, int n_in,
                              void* d_out, int out_size) {
    const float* x    = (const float*)d_in[0];
    const float* W    = (const float*)d_in[1];
    const float* bias = (const float*)d_in[2];
    float* out = (float*)d_out;

    int Ttot = in_sizes[0] / DIM;   // 65536
    int grid = Ttot / BM;           // 512

    cudaFuncSetAttribute((const void*)gate_fused_kernel,
                         cudaFuncAttributeMaxDynamicSharedMemorySize, SMEM_TOTAL);

    prep_wfrag_kernel<<<512, 256>>>(W);
    gate_fused_kernel<<<grid, THREADS, SMEM_TOTAL>>>(x, bias, out, out_size, Ttot);
}

// round 7
// speedup vs baseline: 2.2613x; 1.1171x over previous
#include <cuda_runtime.h>
#include <math.h>
#include <stdint.h>

#define DIM     2048
#define NE      128
#define KSEL    4
#define BM      128     // tokens per CTA
#define KC      32      // K elems per chunk (4 k-steps of 8)
#define NCHUNK  (DIM/KC)
#define THREADS 512
#define LST     129     // logits smem stride
#define ABLK    33      // padded float4 slots per (rowgroup, kstep) block

#define ABUF_BYTES (16 * 4 * ABLK * 16)   // 33792
#define BBUF_BYTES (2048 * 16)            // 32768
#define BOFF       (2 * ABUF_BYTES)       // 67584
#define SOFF       (BOFF + 2 * BBUF_BYTES)            // 133120
#define SMEM_TOTAL (SOFF + 32 * THREADS * 4)          // 198656

// Chunk-major fragment W (hi/lo split): g_Wfrag[((chunk*16 + n8)*4 + ksl)*32 + lane]
//   = {Whi[n8*8+tr][k], Whi[..][k+4], Wlo[..][k], Wlo[..][k+4]},
//   lane = tr*4+tc, k = chunk*32 + ksl*8 + tc
__device__ float4 g_Wfrag[NCHUNK * 2048];   // 2 MB

__device__ __forceinline__ uint32_t smem_u32(const void* p) {
    uint32_t a;
    asm("{ .reg .u64 t; cvta.to.shared.u64 t, %1; cvt.u32.u64 %0, t; }" : "=r"(a) : "l"(p));
    return a;
}
__device__ __forceinline__ void cp_async16(uint32_t dst, const void* src) {
    asm volatile("cp.async.cg.shared.global [%0], [%1], 16;" :: "r"(dst), "l"(src) : "memory");
}
#define CP_COMMIT() asm volatile("cp.async.commit_group;" ::: "memory")
#define CP_WAIT0()  asm volatile("cp.async.wait_group 0;" ::: "memory")

// Split fp32 into tf32 hi + tf32 lo (x = hi + lo + O(2^-33 x))
__device__ __forceinline__ void split_tf32(float v, float& hi, float& lo) {
    unsigned h, l;
    asm("cvt.rna.tf32.f32 %0, %1;" : "=r"(h) : "f"(v));
    hi = __uint_as_float(h);
    float r = v - hi;
    asm("cvt.rna.tf32.f32 %0, %1;" : "=r"(l) : "f"(r));
    lo = __uint_as_float(l);
}

__device__ __forceinline__ void mma_tf32(float c[4],
                                         unsigned a0, unsigned a1, unsigned a2, unsigned a3,
                                         unsigned b0, unsigned b1) {
    asm volatile(
        "mma.sync.aligned.m16n8k8.row.col.f32.tf32.tf32.f32 "
        "{%0,%1,%2,%3}, {%4,%5,%6,%7}, {%8,%9}, {%0,%1,%2,%3};\n"
        : "+f"(c[0]), "+f"(c[1]), "+f"(c[2]), "+f"(c[3])
        : "r"(a0), "r"(a1), "r"(a2), "r"(a3), "r"(b0), "r"(b1));
}

// One-time W -> chunk-major fragment hi/lo split
extern "C" __global__ void prep_wfrag_kernel(const float* __restrict__ W) {
    int t    = blockIdx.x * 256 + threadIdx.x;   // 0..131071
    int lane = t & 31;
    int ksg  = (t >> 5) & 255;                   // global 8-col group
    int n8   = t >> 13;
    int r = n8 * 8 + (lane >> 2);
    int c = ksg * 8 + (lane & 3);
    float h0, l0, h1, l1;
    split_tf32(W[r * DIM + c],     h0, l0);
    split_tf32(W[r * DIM + c + 4], h1, l1);
    int chunk = ksg >> 2, ksl = ksg & 3;
    g_Wfrag[((chunk * 16 + n8) * 4 + ksl) * 32 + lane] = make_float4(h0, h1, l0, l1);
}

// Split prefetched x registers and store fragment-major into A buffer.
__device__ __forceinline__ void store_a(char* abuf, float4 va, float4 vb, int tid) {
    int row = tid >> 2, ksl = tid & 3;
    int rg = row >> 3, tr = row & 7;
    float ha[4], la[4], hb[4], lb[4];
    split_tf32(va.x, ha[0], la[0]); split_tf32(va.y, ha[1], la[1]);
    split_tf32(va.z, ha[2], la[2]); split_tf32(va.w, ha[3], la[3]);
    split_tf32(vb.x, hb[0], lb[0]); split_tf32(vb.y, hb[1], lb[1]);
    split_tf32(vb.z, hb[2], lb[2]); split_tf32(vb.w, hb[3], lb[3]);
    float4* dst = (float4*)abuf + (size_t)((rg * 4 + ksl) * ABLK + ((tr + 2 * ksl) & 7) * 4);
    #pragma unroll
    for (int tc = 0; tc < 4; tc++)
        dst[tc] = make_float4(ha[tc], hb[tc], la[tc], lb[tc]);
}

// Fused: tf32 3-product compensated GEMM (hh + hl + lh) + bias + softmax +
// group-limited top-4. A: LDG-prefetch + split behind compute; B: cp.async staged.
extern "C" __global__ void __launch_bounds__(THREADS, 1)
gate_fused_kernel(const float* __restrict__ x, const float* __restrict__ bias,
                  float* __restrict__ out, int out_size, int Ttot)
{
    extern __shared__ char smem[];
    const uint32_t sb = smem_u32(smem);
    float* s_sm   = (float*)(smem + SOFF);   // TwoSum high parts: [32][THREADS]
    float* logits = (float*)smem;            // reused after GEMM: [128][LST]

    const int tid  = threadIdx.x;
    const int lane = tid & 31;
    const int warp = tid >> 5;
    const int wm   = warp & 3;       // 4 M groups of 32 rows
    const int wn   = warp >> 2;      // 4 N groups of 32 experts
    const long tokBase = (long)blockIdx.x * BM;

    // x pointer for this thread's staging slice (row = tid>>2, cols ksl*8 ..)
    const float* xp = x + (tokBase + (tid >> 2)) * DIM + (tid & 3) * 8;

    float w[2][4][4], c[2][4][4];
    #pragma unroll
    for (int i = 0; i < 2; i++)
        #pragma unroll
        for (int j = 0; j < 4; j++)
            #pragma unroll
            for (int k = 0; k < 4; k++) { w[i][j][k] = 0.f; c[i][j][k] = 0.f; }
    #pragma unroll
    for (int j = 0; j < 32; j++) s_sm[j * THREADS + tid] = 0.f;

    // Prologue: stage chunk 0 (A synchronously, B via cp.async)
    {
        float4 va = *(const float4*)xp;
        float4 vb = *(const float4*)(xp + 4);
        store_a(smem, va, vb, tid);
        const float4* src = g_Wfrag;
        #pragma unroll
        for (int j = 0; j < 4; j++)
            cp_async16(sb + BOFF + (uint32_t)(j * THREADS + tid) * 16, src + j * THREADS + tid);
        CP_COMMIT();
        CP_WAIT0();
    }
    __syncthreads();

    for (int i = 0; i < NCHUNK; i++) {
        // Prefetch next chunk: x into registers (LDG latency hidden behind mma),
        // B via cp.async (completes before the bottom wait+sync).
        float4 xa, xb;
        if (i + 1 < NCHUNK) {
            xa = *(const float4*)(xp + (i + 1) * KC);
            xb = *(const float4*)(xp + (i + 1) * KC + 4);
            const float4* src = g_Wfrag + (size_t)(i + 1) * 2048;
            uint32_t bdst = sb + BOFF + (uint32_t)((i + 1) & 1) * BBUF_BYTES;
            #pragma unroll
            for (int j = 0; j < 4; j++)
                cp_async16(bdst + (uint32_t)(j * THREADS + tid) * 16, src + j * THREADS + tid);
            CP_COMMIT();
        }

        // Compute chunk i
        const float4* Asm = (const float4*)(smem + (i & 1) * ABUF_BYTES);
        const float4* Bsm = (const float4*)(smem + BOFF + (i & 1) * BBUF_BYTES);
        #pragma unroll
        for (int ks = 0; ks < 4; ks++) {
            float4 bf[4];
            #pragma unroll
            for (int nt = 0; nt < 4; nt++)
                bf[nt] = Bsm[((wn * 4 + nt) * 4 + ks) * 32 + lane];
            float4 af0[2], af1[2];
            const int li = (((lane >> 2) + 2 * ks) & 7) * 4 + (lane & 3);
            #pragma unroll
            for (int mt = 0; mt < 2; mt++) {
                int rg = wm * 4 + mt * 2;
                af0[mt] = Asm[(rg * 4 + ks) * ABLK + li];
                af1[mt] = Asm[((rg + 1) * 4 + ks) * ABLK + li];
            }
            #pragma unroll
            for (int nt = 0; nt < 4; nt++) {
                unsigned b0h = __float_as_uint(bf[nt].x), b1h = __float_as_uint(bf[nt].y);
                unsigned b0l = __float_as_uint(bf[nt].z), b1l = __float_as_uint(bf[nt].w);
                #pragma unroll
                for (int mt = 0; mt < 2; mt++) {
                    unsigned a0h = __float_as_uint(af0[mt].x), a2h = __float_as_uint(af0[mt].y);
                    unsigned a0l = __float_as_uint(af0[mt].z), a2l = __float_as_uint(af0[mt].w);
                    unsigned a1h = __float_as_uint(af1[mt].x), a3h = __float_as_uint(af1[mt].y);
                    unsigned a1l = __float_as_uint(af1[mt].z), a3l = __float_as_uint(af1[mt].w);
                    mma_tf32(w[mt][nt], a0h, a1h, a2h, a3h, b0h, b1h);  // hh
                    mma_tf32(c[mt][nt], a0h, a1h, a2h, a3h, b0l, b1l);  // hl
                    mma_tf32(c[mt][nt], a0l, a1l, a2l, a3l, b0h, b1h);  // lh
                }
            }
        }

        // Split + store the prefetched A registers (after compute: LDG hidden)
        if (i + 1 < NCHUNK)
            store_a(smem + ((i + 1) & 1) * ABUF_BYTES, xa, xb, tid);

        // Every 8 chunks (256 k-elems window): TwoSum-fold hh into (s_sm, c)
        if ((i & 7) == 7) {
            #pragma unroll
            for (int mt = 0; mt < 2; mt++)
                #pragma unroll
                for (int nt = 0; nt < 4; nt++)
                    #pragma unroll
                    for (int k = 0; k < 4; k++) {
                        int j = ((mt * 4 + nt) * 4 + k);
                        float p  = w[mt][nt][k];
                        float sv = s_sm[j * THREADS + tid];
                        float z  = __fadd_rn(sv, p);
                        float t  = __fadd_rn(z, -sv);
                        float e1 = __fadd_rn(p, -t);
                        float t2 = __fadd_rn(z, -t);
                        float e2 = __fadd_rn(sv, -t2);
                        c[mt][nt][k] = __fadd_rn(c[mt][nt][k], __fadd_rn(e1, e2));
                        s_sm[j * THREADS + tid] = z;
                        w[mt][nt][k] = 0.f;
                    }
        }
        CP_WAIT0();        // B[i+1] landed
        __syncthreads();   // all reads of buf[i&1] done; buf[(i+1)&1] ready
    }

    // Write logits (+bias) into smem for the fused routing epilogue
    #pragma unroll
    for (int mt = 0; mt < 2; mt++) {
        #pragma unroll
        for (int nt = 0; nt < 4; nt++) {
            int rowb = wm * 32 + mt * 16 + (lane >> 2);
            int colb = wn * 32 + nt * 8 + 2 * (lane & 3);
            float b0v = __ldg(bias + colb), b1v = __ldg(bias + colb + 1);
            #pragma unroll
            for (int half = 0; half < 2; half++) {
                int rw = rowb + half * 8;
                int j0 = ((mt * 4 + nt) * 4 + 2 * half);
                float s0 = s_sm[j0 * THREADS + tid];
                float s1 = s_sm[(j0 + 1) * THREADS + tid];
                float l0 = __fadd_rn(__fadd_rn(s0, c[mt][nt][2*half]),   b0v);
                float l1 = __fadd_rn(__fadd_rn(s1, c[mt][nt][2*half+1]), b1v);
                logits[rw * LST + colb]     = l0;
                logits[rw * LST + colb + 1] = l1;
            }
        }
    }
    __syncthreads();

    // Routing epilogue: 1 thread per token (identical to passing round-2/3/5/6 logic)
    if (tid < BM) {
        const float* row = logits + tid * LST;
        float v1[2], v2[2];
        #pragma unroll
        for (int g = 0; g < 2; g++) {
            float b1 = -INFINITY, b2 = -INFINITY;
            for (int j = 0; j < 64; j++) {
                float v = row[g * 64 + j];
                if (v > b1) { b2 = b1; b1 = v; } else if (v > b2) { b2 = v; }
            }
            v1[g] = b1; v2[g] = b2;
        }
        float m = fmaxf(v1[0], v1[1]);
        double s0 = exp((double)v1[0] - (double)m) + exp((double)v2[0] - (double)m);
        double s1 = exp((double)v1[1] - (double)m) + exp((double)v2[1] - (double)m);
        int gsel = (s1 > s0) ? 1 : 0;     // tie -> lower group index (matches lax.top_k)
        const float* grow = row + gsel * 64;
        unsigned long long used = 0ull;
        float vals[KSEL]; int ids[KSEL];
        #pragma unroll
        for (int p = 0; p < KSEL; p++) {  // sequential argmax: descending, ties -> lower idx
            float best = -INFINITY; int bi = 0;
            for (int j = 0; j < 64; j++) {
                if (!((used >> j) & 1ull)) {
                    float v = grow[j];
                    if (v > best) { best = v; bi = j; }
                }
            }
            used |= (1ull << bi);
            vals[p] = best; ids[p] = gsel * 64 + bi;
        }
        float e[KSEL], ssum = 0.f;
        #pragma unroll
        for (int p = 0; p < KSEL; p++) { e[p] = expf(vals[p] - m); ssum += e[p]; }
        ssum = fmaxf(ssum, 1e-9f);
        long tok = tokBase + tid;
        #pragma unroll
        for (int p = 0; p < KSEL; p++) out[tok * KSEL + p] = e[p] / ssum;
        if (out_size >= 2 * Ttot * KSEL) {   // [w ; idx] layout: indices as floats
            float* oi = out + (long)Ttot * KSEL;
            #pragma unroll
            for (int p = 0; p < KSEL; p++) oi[tok * KSEL + p] = (float)ids[p];
        }
    }
}

extern "C" void kernel_launch(void* const* d_in, const int* in_sizes, int n_in,
                              void* d_out, int out_size) {
    const float* x    = (const float*)d_in[0];
    const float* W    = (const float*)d_in[1];
    const float* bias = (const float*)d_in[2];
    float* out = (float*)d_out;

    int Ttot = in_sizes[0] / DIM;   // 65536
    int grid = Ttot / BM;           // 512

    cudaFuncSetAttribute((const void*)gate_fused_kernel,
                         cudaFuncAttributeMaxDynamicSharedMemorySize, SMEM_TOTAL);

    prep_wfrag_kernel<<<512, 256>>>(W);
    gate_fused_kernel<<<grid, THREADS, SMEM_TOTAL>>>(x, bias, out, out_size, Ttot);
}